// round 7
// baseline (speedup 1.0000x reference)
#include <cuda_runtime.h>
#include <cuda_bf16.h>
#include <mma.h>
#include <cstdint>

using namespace nvcuda;

// Problem constants
#define SS_   128     // MSA depth S  (K of GEMM1)
#define NRES  256     // residues
#define DD    64      // msa dim
#define HH_   32      // proj dim H
#define M_TOT 8192    // N*H
#define KK2   1024    // H*H (K of GEMM2)

// ---------------- device scratch (allocation-free rule) ----------------
__device__ float g_A[SS_ * M_TOT];                  // [s][m] fp32 (prep out)
__device__ float g_B[SS_ * M_TOT];
__device__ __nv_bfloat16 g_Ah[M_TOT * SS_];         // [m][s] K-major bf16 hi/lo
__device__ __nv_bfloat16 g_Al[M_TOT * SS_];
__device__ __nv_bfloat16 g_Bh[M_TOT * SS_];
__device__ __nv_bfloat16 g_Bl[M_TOT * SS_];
// Wo^T packed as 16x16 col-major fragment tiles: [kt(64)][nf(4)] -> 256 elems
// elem (k,n) of tile at n*16+k ; value = Wo[(kt*16+k)*64 + (nf*16+n)]
__device__ __nv_bfloat16 g_Wph[64 * 4 * 256];       // 128 KB
__device__ __nv_bfloat16 g_Wpl[64 * 4 * 256];       // 128 KB
__device__ float g_invden[NRES];

__device__ __forceinline__ void split_bf16(float v, __nv_bfloat16& h, __nv_bfloat16& l) {
    h = __float2bfloat16(v);
    l = __float2bfloat16(v - __bfloat162float(h));
}

__device__ __forceinline__ void cpa16(void* s, const void* g) {
    uint32_t sa = (uint32_t)__cvta_generic_to_shared(s);
    asm volatile("cp.async.cg.shared.global [%0], [%1], 16;" :: "r"(sa), "l"(g));
}
__device__ __forceinline__ void cpa_commit_wait() {
    asm volatile("cp.async.commit_group;" ::: "memory");
    asm volatile("cp.async.wait_group 0;" ::: "memory");
}

// ---------------- combo: Wo fragment-tile pack + denom ----------------
__global__ void __launch_bounds__(256) k_combo(const float* __restrict__ mask,
                                               const float* __restrict__ Wo) {
    int idx = blockIdx.x * 256 + threadIdx.x;     // 65536
    int tile = idx >> 8;          // kt*4+nf
    int within = idx & 255;       // n*16+k
    int kt = tile >> 2, nf = tile & 3;
    int n = within >> 4, k = within & 15;
    int c = kt * 16 + k, p = nf * 16 + n;
    float v = Wo[(size_t)c * 64 + p];
    __nv_bfloat16 h, l; split_bf16(v, h, l);
    g_Wph[idx] = h;
    g_Wpl[idx] = l;

    if (blockIdx.x == 0) {
        int i = threadIdx.x;
        float s = 0.f;
        #pragma unroll 8
        for (int t = 0; t < SS_; ++t) s += mask[t * NRES + i];
        g_invden[i] = 1.0f / fmaxf(s, 1.0f);
    }
}

// ---------------- prep: LN + dual projection + mask + denom fold ----------------
__global__ void __launch_bounds__(256) k_prep(
    const float* __restrict__ x, const float* __restrict__ mask,
    const float* __restrict__ gamma, const float* __restrict__ beta,
    const float* __restrict__ Wa, const float* __restrict__ ba,
    const float* __restrict__ Wb, const float* __restrict__ bb)
{
    __shared__ float sx[8][64];
    int warp = threadIdx.x >> 5, lane = threadIdx.x & 31;
    int row = blockIdx.x * 8 + warp;          // row = s*256 + i
    const float* xr = x + (size_t)row * DD;

    float v0 = xr[lane], v1 = xr[lane + 32];
    float sum = v0 + v1;
    #pragma unroll
    for (int o = 16; o; o >>= 1) sum += __shfl_xor_sync(~0u, sum, o);
    float mu = sum * (1.0f / 64.0f);
    float d0 = v0 - mu, d1 = v1 - mu;
    float vs = d0 * d0 + d1 * d1;
    #pragma unroll
    for (int o = 16; o; o >>= 1) vs += __shfl_xor_sync(~0u, vs, o);
    float rstd = rsqrtf(vs * (1.0f / 64.0f) + 1e-5f);
    sx[warp][lane]      = d0 * rstd * gamma[lane]      + beta[lane];
    sx[warp][lane + 32] = d1 * rstd * gamma[lane + 32] + beta[lane + 32];
    __syncwarp();

    int s = row >> 8, i = row & 255;
    float m = mask[s * NRES + i];
    float a = ba[lane], b = bb[lane];
    #pragma unroll
    for (int d = 0; d < 64; ++d) {
        float xv = sx[warp][d];
        a = fmaf(xv, Wa[d * HH_ + lane], a);
        b = fmaf(xv, Wb[d * HH_ + lane], b);
    }
    a *= m * g_invden[i];
    b *= m;
    g_A[s * M_TOT + i * HH_ + lane] = a;
    g_B[s * M_TOT + i * HH_ + lane] = b;
}

// ---------------- transpose + split: fp32 [s][m] -> bf16 hi/lo [m][s] ----------------
__global__ void k_split_t() {
    __shared__ float t[32][33];
    const float* src = blockIdx.z ? g_B : g_A;
    __nv_bfloat16* oh = blockIdx.z ? g_Bh : g_Ah;
    __nv_bfloat16* ol = blockIdx.z ? g_Bl : g_Al;
    int tx = threadIdx.x, ty = threadIdx.y;
    #pragma unroll
    for (int k = 0; k < 4; ++k) {
        int s = blockIdx.y * 32 + ty + k * 8;
        int m = blockIdx.x * 32 + tx;
        t[ty + k * 8][tx] = src[(size_t)s * M_TOT + m];
    }
    __syncthreads();
    #pragma unroll
    for (int k = 0; k < 4; ++k) {
        int m = blockIdx.x * 32 + ty + k * 8;
        int s = blockIdx.y * 32 + tx;
        float v = t[tx][ty + k * 8];
        __nv_bfloat16 h, l; split_bf16(v, h, l);
        oh[(size_t)m * SS_ + s] = h;
        ol[(size_t)m * SS_ + s] = l;
    }
}

// ===================== FUSED: outer-GEMM (128x128 tile) + @Wo epilogue =====================
#define SK1 72
#define G1_TILE (128 * SK1)           // 9216 elems = 18432 B per tile
#define AE_LD   520                   // bf16 row stride of epilogue A half (512 + pad)
// smem layout (bytes):
//   Phase 1 : [0, 73728)  mainloop tiles sAh|sAl|sBh|sBl
//   Phase 2 : sAe_h [0, 16640) | sAe_l [16640, 33280)
//             sWo_h [33280, 66048) | sWo_l [66048, 98816)
//             scratch [98816, 107008)  (8 warps x 1 KB)
//   Final   : partials [0, 32768)
#define OFF_AEL 16640
#define OFF_WOH 33280
#define OFF_WOL 66048
#define OFF_SCR 98816
#define SMF 107008

__global__ void __launch_bounds__(256, 2) k_fused(const float* __restrict__ bo,
                                                  float* __restrict__ out) {
    extern __shared__ char smc[];
    __nv_bfloat16* sAh = (__nv_bfloat16*)smc;
    __nv_bfloat16* sAl = sAh + G1_TILE;
    __nv_bfloat16* sBh = sAl + G1_TILE;
    __nv_bfloat16* sBl = sBh + G1_TILE;

    int tid = threadIdx.x;
    int wid = tid >> 5, lane = tid & 31;
    int wm = wid & 3, wn = wid >> 2;   // warp tile 32(m) x 64(n)
    int bm = blockIdx.x, bn = blockIdx.y;

    const __nv_bfloat16* gAh = g_Ah + (size_t)bm * 128 * SS_;
    const __nv_bfloat16* gAl = g_Al + (size_t)bm * 128 * SS_;
    const __nv_bfloat16* gBh = g_Bh + (size_t)bn * 128 * SS_;
    const __nv_bfloat16* gBl = g_Bl + (size_t)bn * 128 * SS_;

    wmma::fragment<wmma::accumulator, 16, 16, 16, float> acc[2][4];
    #pragma unroll
    for (int i = 0; i < 2; ++i)
        #pragma unroll
        for (int j = 0; j < 4; ++j) wmma::fill_fragment(acc[i][j], 0.0f);

    // ---------------- Phase 1: outer GEMM mainloop ----------------
    #pragma unroll
    for (int ch = 0; ch < 2; ++ch) {
        int kb = ch * 64;
        #pragma unroll
        for (int it = 0; it < 4; ++it) {
            int idx = it * 256 + tid;        // 1024 segs of 16B
            int row = idx >> 3, seg = idx & 7;
            size_t go = (size_t)row * SS_ + kb + seg * 8;
            int so = row * SK1 + seg * 8;
            cpa16(sAh + so, gAh + go);
            cpa16(sAl + so, gAl + go);
            cpa16(sBh + so, gBh + go);
            cpa16(sBl + so, gBl + go);
        }
        cpa_commit_wait();
        __syncthreads();

        #pragma unroll
        for (int ks = 0; ks < 4; ++ks) {
            wmma::fragment<wmma::matrix_a, 16, 16, 16, __nv_bfloat16, wmma::row_major> ah[2], al[2];
            #pragma unroll
            for (int mf = 0; mf < 2; ++mf) {
                wmma::load_matrix_sync(ah[mf], sAh + (wm * 32 + mf * 16) * SK1 + ks * 16, SK1);
                wmma::load_matrix_sync(al[mf], sAl + (wm * 32 + mf * 16) * SK1 + ks * 16, SK1);
            }
            #pragma unroll
            for (int nf = 0; nf < 4; ++nf) {
                wmma::fragment<wmma::matrix_b, 16, 16, 16, __nv_bfloat16, wmma::col_major> bh, bl;
                wmma::load_matrix_sync(bh, sBh + (wn * 64 + nf * 16) * SK1 + ks * 16, SK1);
                wmma::mma_sync(acc[0][nf], ah[0], bh, acc[0][nf]);
                wmma::mma_sync(acc[1][nf], ah[1], bh, acc[1][nf]);
                wmma::mma_sync(acc[0][nf], al[0], bh, acc[0][nf]);
                wmma::mma_sync(acc[1][nf], al[1], bh, acc[1][nf]);
                wmma::load_matrix_sync(bl, sBl + (wn * 64 + nf * 16) * SK1 + ks * 16, SK1);
                wmma::mma_sync(acc[0][nf], ah[0], bl, acc[0][nf]);
                wmma::mma_sync(acc[1][nf], ah[1], bl, acc[1][nf]);
            }
        }
        __syncthreads();
    }

    // ---------------- Phase 2: epilogue GEMM  C16x64 = Cbig(16x1024) @ Wo ----------------
    // 2 halves (mf) x 2 quarters (16 kt each); Wo quarter staged in smem; acc2 persistent.
    __nv_bfloat16* sAe_h = (__nv_bfloat16*)smc;
    __nv_bfloat16* sAe_l = (__nv_bfloat16*)(smc + OFF_AEL);
    __nv_bfloat16* sWo_h = (__nv_bfloat16*)(smc + OFF_WOH);
    __nv_bfloat16* sWo_l = (__nv_bfloat16*)(smc + OFF_WOL);
    float* sScr = (float*)(smc + OFF_SCR);

    wmma::fragment<wmma::accumulator, 16, 16, 16, float> acc2[4];
    #pragma unroll
    for (int j = 0; j < 4; ++j) wmma::fill_fragment(acc2[j], 0.0f);

    #pragma unroll
    for (int half = 0; half < 2; ++half) {
        // -- convert acc[half][*] -> sAe hi/lo [16][512]
        {
            float* scr = sScr + wid * 256;
            int hr = lane >> 1, kc0 = (lane & 1) * 8;
            #pragma unroll
            for (int nf = 0; nf < 4; ++nf) {
                wmma::store_matrix_sync(scr, acc[half][nf], 16, wmma::mem_row_major);
                __syncwarp();
                const float* p = scr + hr * 16 + kc0;
                uint32_t hp[4], lp[4];
                #pragma unroll
                for (int q = 0; q < 4; ++q) {
                    __nv_bfloat16 h0, l0, h1, l1;
                    split_bf16(p[2 * q], h0, l0);
                    split_bf16(p[2 * q + 1], h1, l1);
                    hp[q] = (uint32_t)__bfloat16_as_ushort(h0) | ((uint32_t)__bfloat16_as_ushort(h1) << 16);
                    lp[q] = (uint32_t)__bfloat16_as_ushort(l0) | ((uint32_t)__bfloat16_as_ushort(l1) << 16);
                }
                int r = wm * 4 + wn * 2 + (nf >> 1);
                int c = hr * 32 + (nf & 1) * 16 + kc0;        // [0, 512)
                *(uint4*)(sAe_h + r * AE_LD + c) = make_uint4(hp[0], hp[1], hp[2], hp[3]);
                *(uint4*)(sAe_l + r * AE_LD + c) = make_uint4(lp[0], lp[1], lp[2], lp[3]);
                __syncwarp();
            }
        }

        #pragma unroll
        for (int sub = 0; sub < 2; ++sub) {
            int q = half * 2 + sub;                            // quarter index
            // -- copy Wo quarter (16 kt x 4 nf) hi+lo into smem, coalesced cp.async
            const __nv_bfloat16* srcH = g_Wph + q * 16384;     // 32768 B
            const __nv_bfloat16* srcL = g_Wpl + q * 16384;
            #pragma unroll
            for (int it = 0; it < 8; ++it) {
                int i = it * 256 + tid;                        // 2048 x 16B
                cpa16((char*)sWo_h + i * 16, (const char*)srcH + i * 16);
                cpa16((char*)sWo_l + i * 16, (const char*)srcL + i * 16);
            }
            cpa_commit_wait();
            __syncthreads();

            // -- MMAs: warp handles local kt t = wid*2 + {0,1}
            #pragma unroll
            for (int tt = 0; tt < 2; ++tt) {
                int t = wid * 2 + tt;                          // [0,16)
                wmma::fragment<wmma::matrix_a, 16, 16, 16, __nv_bfloat16, wmma::row_major> ah, al;
                wmma::load_matrix_sync(ah, sAe_h + sub * 256 + t * 16, AE_LD);
                wmma::load_matrix_sync(al, sAe_l + sub * 256 + t * 16, AE_LD);
                #pragma unroll
                for (int nf = 0; nf < 4; ++nf) {
                    wmma::fragment<wmma::matrix_b, 16, 16, 16, __nv_bfloat16, wmma::col_major> bh, bl;
                    wmma::load_matrix_sync(bh, sWo_h + (t * 4 + nf) * 256, 16);
                    wmma::mma_sync(acc2[nf], ah, bh, acc2[nf]);
                    wmma::mma_sync(acc2[nf], al, bh, acc2[nf]);
                    wmma::load_matrix_sync(bl, sWo_l + (t * 4 + nf) * 256, 16);
                    wmma::mma_sync(acc2[nf], ah, bl, acc2[nf]);
                }
            }
            __syncthreads();
        }
    }

    // ---------------- Final: partial store, cross-warp reduce, +bo, out ----------------
    float* sPart = (float*)smc;
    #pragma unroll
    for (int nf = 0; nf < 4; ++nf)
        wmma::store_matrix_sync(sPart + wid * 1024 + nf * 16, acc2[nf], 64, wmma::mem_row_major);
    __syncthreads();

    {
        int row = tid >> 4;            // 0..15
        int p4  = (tid & 15) * 4;
        float4 s = *(float4*)(sPart + row * 64 + p4);
        #pragma unroll
        for (int w = 1; w < 8; ++w) {
            float4 v = *(float4*)(sPart + w * 1024 + row * 64 + p4);
            s.x += v.x; s.y += v.y; s.z += v.z; s.w += v.w;
        }
        float4 bv = __ldg((const float4*)(bo + p4));
        s.x += bv.x; s.y += bv.y; s.z += bv.z; s.w += bv.w;
        size_t rg = (size_t)(bm * 4 + (row >> 2)) * 256 + bn * 4 + (row & 3);
        *(float4*)(out + rg * 64 + p4) = s;
    }
}

extern "C" void kernel_launch(void* const* d_in, const int* in_sizes, int n_in,
                              void* d_out, int out_size) {
    const float* msa   = (const float*)d_in[0];
    const float* mask  = (const float*)d_in[1];
    const float* gamma = (const float*)d_in[2];
    const float* beta  = (const float*)d_in[3];
    const float* Wa    = (const float*)d_in[4];
    const float* ba    = (const float*)d_in[5];
    const float* Wb    = (const float*)d_in[6];
    const float* bb    = (const float*)d_in[7];
    const float* Wo    = (const float*)d_in[8];
    const float* bo    = (const float*)d_in[9];
    float* out = (float*)d_out;

    cudaFuncSetAttribute(k_fused, cudaFuncAttributeMaxDynamicSharedMemorySize, SMF);

    // order so k_fused is the 4th launch (profiled slot)
    k_combo<<<256, 256>>>(mask, Wo);
    k_prep<<<4096, 256>>>(msa, mask, gamma, beta, Wa, ba, Wb, bb);
    k_split_t<<<dim3(256, 4, 2), dim3(32, 8)>>>();
    k_fused<<<dim3(64, 64), 256, SMF>>>(bo, out);
}

// round 8
// speedup vs baseline: 1.4764x; 1.4764x over previous
#include <cuda_runtime.h>
#include <cuda_bf16.h>
#include <mma.h>
#include <cstdint>

using namespace nvcuda;

// Problem constants
#define SS_   128     // MSA depth S  (K of GEMM1)
#define NRES  256     // residues
#define DD    64      // msa dim
#define HH_   32      // proj dim H
#define M_TOT 8192    // N*H
#define KK2   1024    // H*H (K of GEMM2)

// ---------------- device scratch (allocation-free rule) ----------------
__device__ float g_A[SS_ * M_TOT];                  // [s][m] fp32 (prep out)
__device__ float g_B[SS_ * M_TOT];
__device__ __nv_bfloat16 g_Ah[M_TOT * SS_];         // [m][s] K-major bf16 hi/lo
__device__ __nv_bfloat16 g_Al[M_TOT * SS_];
__device__ __nv_bfloat16 g_Bh[M_TOT * SS_];
__device__ __nv_bfloat16 g_Bl[M_TOT * SS_];
// Wo^T packed as 16x16 col-major fragment tiles: [kt(64)][nf(4)] -> 256 elems
// elem (k,n) of tile at n*16+k ; value = Wo[(kt*16+k)*64 + (nf*16+n)]
__device__ __nv_bfloat16 g_Wph[64 * 4 * 256];       // 128 KB
__device__ __nv_bfloat16 g_Wpl[64 * 4 * 256];       // 128 KB
__device__ float g_invden[NRES];

__device__ __forceinline__ void split_bf16(float v, __nv_bfloat16& h, __nv_bfloat16& l) {
    h = __float2bfloat16(v);
    l = __float2bfloat16(v - __bfloat162float(h));
}

__device__ __forceinline__ void cpa16(void* s, const void* g) {
    uint32_t sa = (uint32_t)__cvta_generic_to_shared(s);
    asm volatile("cp.async.cg.shared.global [%0], [%1], 16;" :: "r"(sa), "l"(g));
}
__device__ __forceinline__ void cpa_commit() {
    asm volatile("cp.async.commit_group;" ::: "memory");
}
template <int N>
__device__ __forceinline__ void cpa_wait() {
    asm volatile("cp.async.wait_group %0;" :: "n"(N) : "memory");
}

// ---------------- combo: Wo fragment-tile pack + denom ----------------
__global__ void __launch_bounds__(256) k_combo(const float* __restrict__ mask,
                                               const float* __restrict__ Wo) {
    int idx = blockIdx.x * 256 + threadIdx.x;     // 65536
    int tile = idx >> 8;          // kt*4+nf
    int within = idx & 255;       // n*16+k
    int kt = tile >> 2, nf = tile & 3;
    int n = within >> 4, k = within & 15;
    int c = kt * 16 + k, p = nf * 16 + n;
    float v = Wo[(size_t)c * 64 + p];
    __nv_bfloat16 h, l; split_bf16(v, h, l);
    g_Wph[idx] = h;
    g_Wpl[idx] = l;

    if (blockIdx.x == 0) {
        int i = threadIdx.x;
        float s = 0.f;
        #pragma unroll 8
        for (int t = 0; t < SS_; ++t) s += mask[t * NRES + i];
        g_invden[i] = 1.0f / fmaxf(s, 1.0f);
    }
}

// ---------------- prep: LN + dual projection + mask + denom fold ----------------
__global__ void __launch_bounds__(256) k_prep(
    const float* __restrict__ x, const float* __restrict__ mask,
    const float* __restrict__ gamma, const float* __restrict__ beta,
    const float* __restrict__ Wa, const float* __restrict__ ba,
    const float* __restrict__ Wb, const float* __restrict__ bb)
{
    __shared__ float sx[8][64];
    int warp = threadIdx.x >> 5, lane = threadIdx.x & 31;
    int row = blockIdx.x * 8 + warp;          // row = s*256 + i
    const float* xr = x + (size_t)row * DD;

    float v0 = xr[lane], v1 = xr[lane + 32];
    float sum = v0 + v1;
    #pragma unroll
    for (int o = 16; o; o >>= 1) sum += __shfl_xor_sync(~0u, sum, o);
    float mu = sum * (1.0f / 64.0f);
    float d0 = v0 - mu, d1 = v1 - mu;
    float vs = d0 * d0 + d1 * d1;
    #pragma unroll
    for (int o = 16; o; o >>= 1) vs += __shfl_xor_sync(~0u, vs, o);
    float rstd = rsqrtf(vs * (1.0f / 64.0f) + 1e-5f);
    sx[warp][lane]      = d0 * rstd * gamma[lane]      + beta[lane];
    sx[warp][lane + 32] = d1 * rstd * gamma[lane + 32] + beta[lane + 32];
    __syncwarp();

    int s = row >> 8, i = row & 255;
    float m = mask[s * NRES + i];
    float a = ba[lane], b = bb[lane];
    #pragma unroll
    for (int d = 0; d < 64; ++d) {
        float xv = sx[warp][d];
        a = fmaf(xv, Wa[d * HH_ + lane], a);
        b = fmaf(xv, Wb[d * HH_ + lane], b);
    }
    a *= m * g_invden[i];
    b *= m;
    g_A[s * M_TOT + i * HH_ + lane] = a;
    g_B[s * M_TOT + i * HH_ + lane] = b;
}

// ---------------- transpose + split: fp32 [s][m] -> bf16 hi/lo [m][s] ----------------
__global__ void k_split_t() {
    __shared__ float t[32][33];
    const float* src = blockIdx.z ? g_B : g_A;
    __nv_bfloat16* oh = blockIdx.z ? g_Bh : g_Ah;
    __nv_bfloat16* ol = blockIdx.z ? g_Bl : g_Al;
    int tx = threadIdx.x, ty = threadIdx.y;
    #pragma unroll
    for (int k = 0; k < 4; ++k) {
        int s = blockIdx.y * 32 + ty + k * 8;
        int m = blockIdx.x * 32 + tx;
        t[ty + k * 8][tx] = src[(size_t)s * M_TOT + m];
    }
    __syncthreads();
    #pragma unroll
    for (int k = 0; k < 4; ++k) {
        int m = blockIdx.x * 32 + ty + k * 8;
        int s = blockIdx.y * 32 + tx;
        float v = t[tx][ty + k * 8];
        __nv_bfloat16 h, l; split_bf16(v, h, l);
        oh[(size_t)m * SS_ + s] = h;
        ol[(size_t)m * SS_ + s] = l;
    }
}

// ===================== FUSED: outer-GEMM (128x128 tile) + @Wo epilogue =====================
// Mainloop: K-chunk 32, 4 chunks, 2-stage cp.async double buffer.
// Tile row stride 40 bf16 (80 B) -> LDSM conflict-free.
#define SKC 40
#define TILE_B (128 * SKC * 2)        // 10240 B per tensor-tile per stage
#define STAGE_B (4 * TILE_B)          // 40960 B per stage
#define AE_LD 1032
// smem (bytes):
//   Mainloop: stage0 [0,40960) | stage1 [40960,81920)
//   Epilogue: sAe_h [0,33024) | sAe_l [33024,66048) | scr/partials [66048,98816)
#define SMF 98816

__global__ void __launch_bounds__(256, 2) k_fused(const float* __restrict__ bo,
                                                  float* __restrict__ out) {
    extern __shared__ char smc[];
    int tid = threadIdx.x;
    int wid = tid >> 5, lane = tid & 31;
    int wm = wid & 3, wn = wid >> 2;   // warp tile 32(m) x 64(n)
    int bm = blockIdx.x, bn = blockIdx.y;

    const __nv_bfloat16* gAh = g_Ah + (size_t)bm * 128 * SS_;
    const __nv_bfloat16* gAl = g_Al + (size_t)bm * 128 * SS_;
    const __nv_bfloat16* gBh = g_Bh + (size_t)bn * 128 * SS_;
    const __nv_bfloat16* gBl = g_Bl + (size_t)bn * 128 * SS_;

    wmma::fragment<wmma::accumulator, 16, 16, 16, float> acc[2][4];
    #pragma unroll
    for (int i = 0; i < 2; ++i)
        #pragma unroll
        for (int j = 0; j < 4; ++j) wmma::fill_fragment(acc[i][j], 0.0f);

    // stage tile load: 512 segs/tensor (128 rows x 4 segs of 8 bf16), 2 per thread
    auto load_stage = [&](int stage, int ch) {
        char* base = smc + stage * STAGE_B;
        __nv_bfloat16* dAh = (__nv_bfloat16*)base;
        __nv_bfloat16* dAl = dAh + 128 * SKC;
        __nv_bfloat16* dBh = dAl + 128 * SKC;
        __nv_bfloat16* dBl = dBh + 128 * SKC;
        int kb = ch * 32;
        #pragma unroll
        for (int it = 0; it < 2; ++it) {
            int idx = it * 256 + tid;
            int row = idx >> 2, seg = idx & 3;
            size_t go = (size_t)row * SS_ + kb + seg * 8;
            int so = row * SKC + seg * 8;
            cpa16(dAh + so, gAh + go);
            cpa16(dAl + so, gAl + go);
            cpa16(dBh + so, gBh + go);
            cpa16(dBl + so, gBl + go);
        }
        cpa_commit();
    };

    // ---------------- Phase 1: pipelined mainloop ----------------
    load_stage(0, 0);
    #pragma unroll
    for (int ch = 0; ch < 4; ++ch) {
        int cur = ch & 1;
        if (ch < 3) load_stage(cur ^ 1, ch + 1);
        if (ch < 3) cpa_wait<1>(); else cpa_wait<0>();
        __syncthreads();

        char* base = smc + cur * STAGE_B;
        __nv_bfloat16* sAh = (__nv_bfloat16*)base;
        __nv_bfloat16* sAl = sAh + 128 * SKC;
        __nv_bfloat16* sBh = sAl + 128 * SKC;
        __nv_bfloat16* sBl = sBh + 128 * SKC;

        #pragma unroll
        for (int ks = 0; ks < 2; ++ks) {
            wmma::fragment<wmma::matrix_a, 16, 16, 16, __nv_bfloat16, wmma::row_major> ah[2], al[2];
            #pragma unroll
            for (int mf = 0; mf < 2; ++mf) {
                wmma::load_matrix_sync(ah[mf], sAh + (wm * 32 + mf * 16) * SKC + ks * 16, SKC);
                wmma::load_matrix_sync(al[mf], sAl + (wm * 32 + mf * 16) * SKC + ks * 16, SKC);
            }
            #pragma unroll
            for (int nf = 0; nf < 4; ++nf) {
                wmma::fragment<wmma::matrix_b, 16, 16, 16, __nv_bfloat16, wmma::col_major> bh, bl;
                wmma::load_matrix_sync(bh, sBh + (wn * 64 + nf * 16) * SKC + ks * 16, SKC);
                wmma::mma_sync(acc[0][nf], ah[0], bh, acc[0][nf]);
                wmma::mma_sync(acc[1][nf], ah[1], bh, acc[1][nf]);
                wmma::mma_sync(acc[0][nf], al[0], bh, acc[0][nf]);
                wmma::mma_sync(acc[1][nf], al[1], bh, acc[1][nf]);
                wmma::load_matrix_sync(bl, sBl + (wn * 64 + nf * 16) * SKC + ks * 16, SKC);
                wmma::mma_sync(acc[0][nf], ah[0], bl, acc[0][nf]);
                wmma::mma_sync(acc[1][nf], ah[1], bl, acc[1][nf]);
            }
        }
        __syncthreads();
    }

    // ---------------- Phase 2a: convert frags -> sAe hi/lo [16][1024] ----------------
    __nv_bfloat16* sAe_h = (__nv_bfloat16*)smc;
    __nv_bfloat16* sAe_l = sAe_h + 16 * AE_LD;
    float* sScr  = (float*)(smc + 66048);
    float* sPart = (float*)(smc + 66048);
    {
        float* scr = sScr + wid * 256;
        int hr = lane >> 1, kc0 = (lane & 1) * 8;
        #pragma unroll
        for (int mf = 0; mf < 2; ++mf)
            #pragma unroll
            for (int nf = 0; nf < 4; ++nf) {
                wmma::store_matrix_sync(scr, acc[mf][nf], 16, wmma::mem_row_major);
                __syncwarp();
                const float* p = scr + hr * 16 + kc0;
                uint32_t hp[4], lp[4];
                #pragma unroll
                for (int q = 0; q < 4; ++q) {
                    __nv_bfloat16 h0, l0, h1, l1;
                    split_bf16(p[2 * q], h0, l0);
                    split_bf16(p[2 * q + 1], h1, l1);
                    hp[q] = (uint32_t)__bfloat16_as_ushort(h0) | ((uint32_t)__bfloat16_as_ushort(h1) << 16);
                    lp[q] = (uint32_t)__bfloat16_as_ushort(l0) | ((uint32_t)__bfloat16_as_ushort(l1) << 16);
                }
                int r = wm * 4 + wn * 2 + (nf >> 1);
                int c = mf * 512 + hr * 32 + (nf & 1) * 16 + kc0;
                *(uint4*)(sAe_h + r * AE_LD + c) = make_uint4(hp[0], hp[1], hp[2], hp[3]);
                *(uint4*)(sAe_l + r * AE_LD + c) = make_uint4(lp[0], lp[1], lp[2], lp[3]);
                __syncwarp();
            }
    }
    __syncthreads();

    // ---------------- Phase 2b: C16x64 = sAe @ Wo (warp-split K, batched global frag loads) ----------------
    {
        wmma::fragment<wmma::accumulator, 16, 16, 16, float> acc2[4];
        #pragma unroll
        for (int j = 0; j < 4; ++j) wmma::fill_fragment(acc2[j], 0.0f);

        #pragma unroll
        for (int ks = 0; ks < 8; ++ks) {
            int kt = wid * 8 + ks;
            int kk = kt * 16;
            // batch all 8 independent Wo frag loads first (MLP)
            wmma::fragment<wmma::matrix_b, 16, 16, 16, __nv_bfloat16, wmma::col_major> bh[4], bl[4];
            #pragma unroll
            for (int nf = 0; nf < 4; ++nf) {
                wmma::load_matrix_sync(bh[nf], g_Wph + (kt * 4 + nf) * 256, 16);
                wmma::load_matrix_sync(bl[nf], g_Wpl + (kt * 4 + nf) * 256, 16);
            }
            wmma::fragment<wmma::matrix_a, 16, 16, 16, __nv_bfloat16, wmma::row_major> ah, al;
            wmma::load_matrix_sync(ah, sAe_h + kk, AE_LD);
            wmma::load_matrix_sync(al, sAe_l + kk, AE_LD);
            #pragma unroll
            for (int nf = 0; nf < 4; ++nf) {
                wmma::mma_sync(acc2[nf], ah, bh[nf], acc2[nf]);
                wmma::mma_sync(acc2[nf], al, bh[nf], acc2[nf]);
                wmma::mma_sync(acc2[nf], ah, bl[nf], acc2[nf]);
            }
        }
        __syncthreads();
        #pragma unroll
        for (int nf = 0; nf < 4; ++nf)
            wmma::store_matrix_sync(sPart + wid * 1024 + nf * 16, acc2[nf], 64, wmma::mem_row_major);
    }
    __syncthreads();

    // ---------------- Phase 2c: reduce 8 partials, +bo, store ----------------
    {
        int row = tid >> 4;            // 0..15
        int p4  = (tid & 15) * 4;
        float4 s = *(float4*)(sPart + row * 64 + p4);
        #pragma unroll
        for (int w = 1; w < 8; ++w) {
            float4 v = *(float4*)(sPart + w * 1024 + row * 64 + p4);
            s.x += v.x; s.y += v.y; s.z += v.z; s.w += v.w;
        }
        float4 bv = __ldg((const float4*)(bo + p4));
        s.x += bv.x; s.y += bv.y; s.z += bv.z; s.w += bv.w;
        size_t rg = (size_t)(bm * 4 + (row >> 2)) * 256 + bn * 4 + (row & 3);
        *(float4*)(out + rg * 64 + p4) = s;
    }
}

extern "C" void kernel_launch(void* const* d_in, const int* in_sizes, int n_in,
                              void* d_out, int out_size) {
    const float* msa   = (const float*)d_in[0];
    const float* mask  = (const float*)d_in[1];
    const float* gamma = (const float*)d_in[2];
    const float* beta  = (const float*)d_in[3];
    const float* Wa    = (const float*)d_in[4];
    const float* ba    = (const float*)d_in[5];
    const float* Wb    = (const float*)d_in[6];
    const float* bb    = (const float*)d_in[7];
    const float* Wo    = (const float*)d_in[8];
    const float* bo    = (const float*)d_in[9];
    float* out = (float*)d_out;

    cudaFuncSetAttribute(k_fused, cudaFuncAttributeMaxDynamicSharedMemorySize, SMF);

    // order so k_fused is the 4th launch (profiled slot)
    k_combo<<<256, 256>>>(mask, Wo);
    k_prep<<<4096, 256>>>(msa, mask, gamma, beta, Wa, ba, Wb, bb);
    k_split_t<<<dim3(256, 4, 2), dim3(32, 8)>>>();
    k_fused<<<dim3(64, 64), 256, SMF>>>(bo, out);
}